// round 16
// baseline (speedup 1.0000x reference)
#include <cuda_runtime.h>
#include <cuda_bf16.h>

#define VOCAB 50000
#define D 256
#define E 20000
#define L 20

// ---------------- scratch (static device globals; no allocation) ----------------
__device__ float g_qemb[D];
__device__ float g_g0[D];
__device__ float g_g1[D];
__device__ float g_u[VOCAB];
__device__ float g_w[VOCAB];
__device__ __align__(16) float g_A[VOCAB];
__device__ __align__(16) float g_B[VOCAB];
__device__ float g_accA[D];
__device__ float g_accB[D];
__device__ float g_wte1[D];
__device__ float g_sumw;
__device__ float g_sumexp;

__device__ __forceinline__ float warp_sum(float v) {
    #pragma unroll
    for (int o = 16; o > 0; o >>= 1) v += __shfl_xor_sync(0xffffffffu, v, o);
    return v;
}

__device__ __forceinline__ float dot8(float4 x0, float4 x1, float4 c0, float4 c1) {
    return x0.x*c0.x + x0.y*c0.y + x0.z*c0.z + x0.w*c0.w
         + x1.x*c1.x + x1.y*c1.y + x1.z*c1.z + x1.w*c1.w;
}

// ---- bulk-TMA + mbarrier helpers (CUTLASS-exact instruction forms) --------------
__device__ __forceinline__ unsigned smem_u32(const void* p) {
    return (unsigned)__cvta_generic_to_shared(p);
}
__device__ __forceinline__ void mbar_init(unsigned mbar, unsigned cnt) {
    asm volatile("mbarrier.init.shared::cta.b64 [%0], %1;" :: "r"(mbar), "r"(cnt) : "memory");
}
__device__ __forceinline__ void mbar_expect_tx(unsigned mbar, unsigned bytes) {
    asm volatile("mbarrier.arrive.expect_tx.shared::cta.b64 _, [%0], %1;"
                 :: "r"(mbar), "r"(bytes) : "memory");
}
__device__ __forceinline__ void tma_bulk_g2s(unsigned sdst, const void* gsrc,
                                             unsigned bytes, unsigned mbar) {
    asm volatile("cp.async.bulk.shared::cluster.global.mbarrier::complete_tx::bytes "
                 "[%0], [%1], %2, [%3];"
                 :: "r"(sdst), "l"(gsrc), "r"(bytes), "r"(mbar) : "memory");
}
__device__ __forceinline__ void mbar_wait(unsigned mbar, unsigned parity) {
    asm volatile("{\n\t"
                 ".reg .pred P;\n\t"
                 "WAIT%=:\n\t"
                 "mbarrier.try_wait.parity.shared::cta.b64 P, [%0], %1;\n\t"
                 "@!P bra WAIT%=;\n\t"
                 "}" :: "r"(mbar), "r"(parity) : "memory");
}

#define TGRID   888                  // ~6 CTAs/SM
#define TCR     16                   // rows per chunk (16KB)
#define TCB     (TCR * D * 4)        // bytes per chunk
#define TNCH    (VOCAB / TCR)        // 3125 chunks
#define NST     2                    // pipeline stages (32KB smem)

// ---------------- K1: q_emb + derived vectors, zero accumulators ----------------
__global__ void k1_qemb(const int* __restrict__ question,
                        const float* __restrict__ q_table) {
    int d = threadIdx.x;                         // 256 threads
    float a  = 1.0f - (float)d * (1.0f / D);
    float be = 2.0f * (float)d * (1.0f / D) - 1.0f;
    float s = 0.0f;
    #pragma unroll
    for (int l = 0; l < L; ++l) {
        int v = question[l];
        float pe = a + ((float)l * (1.0f / L)) * be;
        s += __ldg(&q_table[(size_t)v * D + d]) * pe;
    }
    g_qemb[d] = s;
    g_g0[d] = a * s;
    g_g1[d] = be * s;
    g_accA[d] = 0.0f; g_accB[d] = 0.0f; g_wte1[d] = 0.0f;
    if (d == 0) { g_sumw = 0.0f; g_sumexp = 0.0f; }
}

// ---------------- K2: u[v], w[v] over q_table via bulk-TMA; zero A/B -------------
__global__ void k2_uw(const float* __restrict__ q_table) {
    __shared__ __align__(128) float buf[NST][TCR * D];
    __shared__ __align__(8) unsigned long long mbar_s[NST];
    __shared__ float4 s0[64], s1[64];
    int t = threadIdx.x;                      // 256
    int warp = t >> 5, lane = t & 31;
    unsigned mb0 = smem_u32(&mbar_s[0]);
    unsigned mb1 = smem_u32(&mbar_s[1]);
    if (t == 0) { mbar_init(mb0, 1); mbar_init(mb1, 1); }
    if (t < 64) {
        s0[t] = ((const float4*)g_g0)[t];
        s1[t] = ((const float4*)g_g1)[t];
    }
    __syncthreads();
    if (t == 0) {
        #pragma unroll
        for (int s = 0; s < NST; ++s) {
            int c = blockIdx.x + s * TGRID;
            if (c < TNCH) {
                unsigned mb = s ? mb1 : mb0;
                mbar_expect_tx(mb, TCB);
                tma_bulk_g2s(smem_u32(buf[s]), q_table + (size_t)c * TCR * D, TCB, mb);
            }
        }
    }
    float4 c0 = s0[lane], c1 = s0[lane + 32];
    float4 d0 = s1[lane], d1 = s1[lane + 32];
    int i = 0;
    for (int c = blockIdx.x; c < TNCH; c += TGRID, ++i) {
        int stage = i & 1;
        int parity = (i >> 1) & 1;
        unsigned mb = stage ? mb1 : mb0;
        mbar_wait(mb, parity);
        const float4* bf = (const float4*)buf[stage];
        float4 xa0 = bf[(warp * 2) * 64 + lane];
        float4 xa1 = bf[(warp * 2) * 64 + lane + 32];
        float4 xb0 = bf[(warp * 2 + 1) * 64 + lane];
        float4 xb1 = bf[(warp * 2 + 1) * 64 + lane + 32];
        __syncthreads();                      // reads complete -> refill early
        if (t == 0) {
            int cn = c + NST * TGRID;
            if (cn < TNCH) {
                mbar_expect_tx(mb, TCB);
                tma_bulk_g2s(smem_u32(buf[stage]), q_table + (size_t)cn * TCR * D, TCB, mb);
            }
        }
        float u0 = dot8(xa0, xa1, c0, c1);
        float w0 = dot8(xa0, xa1, d0, d1);
        float u1 = dot8(xb0, xb1, c0, c1);
        float w1 = dot8(xb0, xb1, d0, d1);
        u0 = warp_sum(u0); w0 = warp_sum(w0);
        u1 = warp_sum(u1); w1 = warp_sum(w1);
        int vbase = c * TCR + warp * 2;
        if (lane == 0) {
            g_u[vbase] = u0;     g_w[vbase] = w0;
            g_u[vbase + 1] = u1; g_w[vbase + 1] = w1;
        }
        if (t < TCR) { g_A[c * TCR + t] = 0.0f; g_B[c * TCR + t] = 0.0f; }
    }
}

// ---------------- K34: fused scores + exp + A/B scatter + weights@te1 ------------
#define K34_CHUNK  32
#define K34_BLOCKS (E / K34_CHUNK)    // 625
__global__ void k34_weights(const int* __restrict__ evidence,
                            const float* __restrict__ te2,
                            const float* __restrict__ te1) {
    __shared__ float4 sq[64];
    __shared__ float s_w[K34_CHUNK];
    int t = threadIdx.x;                      // 256
    int warp = t >> 5, lane = t & 31;
    if (t < 64) sq[t] = ((const float4*)g_qemb)[t];
    __syncthreads();
    int e0 = blockIdx.x * K34_CHUNK;
    float4 q0 = sq[lane], q1 = sq[lane + 32];
    float part[4];
    #pragma unroll
    for (int r = 0; r < 4; ++r) {
        int e = e0 + warp * 4 + r;
        float p = 0.0f;
        if (lane < L) {
            int v = __ldg(&evidence[e * L + lane]);
            p = g_u[v] + ((float)lane * (1.0f / L)) * g_w[v];
        }
        const float4* row = (const float4*)(te2 + (size_t)e * D);
        float4 x0 = __ldg(&row[lane]);
        float4 x1 = __ldg(&row[lane + 32]);
        part[r] = p + dot8(x0, x1, q0, q1);
    }
    #pragma unroll
    for (int r = 0; r < 4; ++r) part[r] = warp_sum(part[r]);
    if (lane == 0) {
        #pragma unroll
        for (int r = 0; r < 4; ++r) s_w[warp * 4 + r] = part[r];
    }
    __syncthreads();
    if (t < 32) {
        float w = expf(s_w[t]);
        s_w[t] = w;
        float s = warp_sum(w);
        if (t == 0) atomicAdd(&g_sumw, s);
    }
    __syncthreads();
    for (int i = t; i < K34_CHUNK * L; i += 256) {
        int el = i / L;
        int l  = i - el * L;
        int v  = __ldg(&evidence[(e0 + el) * L + l]);
        float w = s_w[el];
        atomicAdd(&g_A[v], w);
        atomicAdd(&g_B[v], w * ((float)l * (1.0f / L)));
    }
    int d = t;
    float acc = 0.0f;
    #pragma unroll 8
    for (int el = 0; el < K34_CHUNK; ++el)
        acc += s_w[el] * __ldg(&te1[(size_t)(e0 + el) * D + d]);
    atomicAdd(&g_wte1[d], acc);
}

// ---------------- K5: accA/accB = A@e_table, B@e_table (bulk-TMA, early refill) --
__global__ void k5_etable(const float* __restrict__ e_table) {
    __shared__ __align__(128) float buf[NST][TCR * D];
    __shared__ __align__(8) unsigned long long mbar_s[NST];
    int t = threadIdx.x;                      // 256 (= column)
    unsigned mb0 = smem_u32(&mbar_s[0]);
    unsigned mb1 = smem_u32(&mbar_s[1]);
    if (t == 0) { mbar_init(mb0, 1); mbar_init(mb1, 1); }
    __syncthreads();
    if (t == 0) {
        #pragma unroll
        for (int s = 0; s < NST; ++s) {
            int c = blockIdx.x + s * TGRID;
            if (c < TNCH) {
                unsigned mb = s ? mb1 : mb0;
                mbar_expect_tx(mb, TCB);
                tma_bulk_g2s(smem_u32(buf[s]), e_table + (size_t)c * TCR * D, TCB, mb);
            }
        }
    }
    float a = 0.0f, b = 0.0f;
    int i = 0;
    for (int c = blockIdx.x; c < TNCH; c += TGRID, ++i) {
        int stage = i & 1;
        int parity = (i >> 1) & 1;
        unsigned mb = stage ? mb1 : mb0;
        int v0 = c * TCR;
        float4 A0 = __ldg((const float4*)&g_A[v0]);
        float4 A1 = __ldg((const float4*)&g_A[v0 + 4]);
        float4 A2 = __ldg((const float4*)&g_A[v0 + 8]);
        float4 A3 = __ldg((const float4*)&g_A[v0 + 12]);
        float4 B0 = __ldg((const float4*)&g_B[v0]);
        float4 B1 = __ldg((const float4*)&g_B[v0 + 4]);
        float4 B2 = __ldg((const float4*)&g_B[v0 + 8]);
        float4 B3 = __ldg((const float4*)&g_B[v0 + 12]);
        mbar_wait(mb, parity);
        const float* base = buf[stage] + t;
        float x0  = base[0 * D],  x1  = base[1 * D],  x2  = base[2 * D],  x3  = base[3 * D];
        float x4  = base[4 * D],  x5  = base[5 * D],  x6  = base[6 * D],  x7  = base[7 * D];
        float x8  = base[8 * D],  x9  = base[9 * D],  x10 = base[10 * D], x11 = base[11 * D];
        float x12 = base[12 * D], x13 = base[13 * D], x14 = base[14 * D], x15 = base[15 * D];
        __syncthreads();                      // reads complete -> refill early
        if (t == 0) {
            int cn = c + NST * TGRID;
            if (cn < TNCH) {
                mbar_expect_tx(mb, TCB);
                tma_bulk_g2s(smem_u32(buf[stage]), e_table + (size_t)cn * TCR * D, TCB, mb);
            }
        }
        a += A0.x*x0 + A0.y*x1 + A0.z*x2 + A0.w*x3
           + A1.x*x4 + A1.y*x5 + A1.z*x6 + A1.w*x7
           + A2.x*x8 + A2.y*x9 + A2.z*x10 + A2.w*x11
           + A3.x*x12 + A3.y*x13 + A3.z*x14 + A3.w*x15;
        b += B0.x*x0 + B0.y*x1 + B0.z*x2 + B0.w*x3
           + B1.x*x4 + B1.y*x5 + B1.z*x6 + B1.w*x7
           + B2.x*x8 + B2.y*x9 + B2.z*x10 + B2.w*x11
           + B3.x*x12 + B3.y*x13 + B3.z*x14 + B3.w*x15;
    }
    atomicAdd(&g_accA[t], a);
    atomicAdd(&g_accB[t], b);
}

// ---------------- K6: logits + exp + sumexp (bulk-TMA over W, early refill) ------
__global__ void k6_logits(const float* __restrict__ W, const float* __restrict__ bb,
                          float* __restrict__ out) {
    __shared__ __align__(128) float buf[NST][TCR * D];
    __shared__ __align__(8) unsigned long long mbar_s[NST];
    __shared__ float s_feat[D];
    __shared__ float s_p[8];
    int t = threadIdx.x;                      // 256
    int warp = t >> 5, lane = t & 31;
    unsigned mb0 = smem_u32(&mbar_s[0]);
    unsigned mb1 = smem_u32(&mbar_s[1]);
    if (t == 0) { mbar_init(mb0, 1); mbar_init(mb1, 1); }
    {
        float a  = 1.0f - (float)t * (1.0f / D);
        float be = 2.0f * (float)t * (1.0f / D) - 1.0f;
        float invS = 1.0f / g_sumw;
        s_feat[t] = (a * g_accA[t] + be * g_accB[t] + g_wte1[t]) * invS + g_qemb[t];
    }
    __syncthreads();
    if (t == 0) {
        #pragma unroll
        for (int s = 0; s < NST; ++s) {
            int c = blockIdx.x + s * TGRID;
            if (c < TNCH) {
                unsigned mb = s ? mb1 : mb0;
                mbar_expect_tx(mb, TCB);
                tma_bulk_g2s(smem_u32(buf[s]), W + (size_t)c * TCR * D, TCB, mb);
            }
        }
    }
    const float4* sf = (const float4*)s_feat;
    float4 f0 = sf[lane], f1 = sf[lane + 32];
    float p_sum = 0.0f;
    int i = 0;
    for (int c = blockIdx.x; c < TNCH; c += TGRID, ++i) {
        int stage = i & 1;
        int parity = (i >> 1) & 1;
        unsigned mb = stage ? mb1 : mb0;
        int vbase = c * TCR + warp * 2;
        float bias0 = __ldg(&bb[vbase]);
        float bias1 = __ldg(&bb[vbase + 1]);
        mbar_wait(mb, parity);
        const float4* bf = (const float4*)buf[stage];
        float4 xa0 = bf[(warp * 2) * 64 + lane];
        float4 xa1 = bf[(warp * 2) * 64 + lane + 32];
        float4 xb0 = bf[(warp * 2 + 1) * 64 + lane];
        float4 xb1 = bf[(warp * 2 + 1) * 64 + lane + 32];
        __syncthreads();                      // reads complete -> refill early
        if (t == 0) {
            int cn = c + NST * TGRID;
            if (cn < TNCH) {
                mbar_expect_tx(mb, TCB);
                tma_bulk_g2s(smem_u32(buf[stage]), W + (size_t)cn * TCR * D, TCB, mb);
            }
        }
        float s0 = dot8(xa0, xa1, f0, f1);
        float s1 = dot8(xb0, xb1, f0, f1);
        s0 = warp_sum(s0); s1 = warp_sum(s1);
        if (lane == 0) {
            float p0 = expf(s0 + bias0);
            float p1 = expf(s1 + bias1);
            out[vbase] = p0;                  // unnormalized
            out[vbase + 1] = p1;
            p_sum += p0 + p1;
        }
    }
    if (lane == 0) s_p[warp] = p_sum;
    __syncthreads();
    if (t < 8) {
        float x = s_p[t];
        #pragma unroll
        for (int o = 4; o > 0; o >>= 1) x += __shfl_xor_sync(0xffu, x, o);
        if (t == 0) atomicAdd(&g_sumexp, x);
    }
}

// ---------------- K7: normalize output (float4) ----------------------------------
__global__ void k7_scale(float* __restrict__ out) {
    int i = blockIdx.x * blockDim.x + threadIdx.x;   // VOCAB/4 = 12500 float4
    float inv = 1.0f / g_sumexp;
    if (i < VOCAB / 4) {
        float4 v = ((const float4*)out)[i];
        v.x *= inv; v.y *= inv; v.z *= inv; v.w *= inv;
        ((float4*)out)[i] = v;
    }
}

// ---------------- launch ---------------------------------------------------------
extern "C" void kernel_launch(void* const* d_in, const int* in_sizes, int n_in,
                              void* d_out, int out_size) {
    const int*   evidence = (const int*)  d_in[0];
    const int*   question = (const int*)  d_in[1];
    const float* q_table  = (const float*)d_in[2];
    const float* e_table  = (const float*)d_in[3];
    const float* te1      = (const float*)d_in[4];
    const float* te2      = (const float*)d_in[5];
    const float* W        = (const float*)d_in[6];
    const float* b        = (const float*)d_in[7];
    float* out = (float*)d_out;

    k1_qemb<<<1, 256>>>(question, q_table);
    k2_uw<<<TGRID, 256>>>(q_table);
    k34_weights<<<K34_BLOCKS, 256>>>(evidence, te2, te1);
    k5_etable<<<TGRID, 256>>>(e_table);
    k6_logits<<<TGRID, 256>>>(W, b, out);
    k7_scale<<<(VOCAB / 4 + 255) / 256, 256>>>(out);
}